// round 15
// baseline (speedup 1.0000x reference)
#include <cuda_runtime.h>
#include <math.h>

#define NN 100000
#define EE 1600000

// ---------------- scratch (device globals) ----------------
__device__ float g_h[NN * 64];
__device__ float g_x[NN * 64];
__device__ float g_aggr[NN * 64];
__device__ float g_deg[NN];
__device__ float g_dinv[NN];
__device__ float g_stats[152];
__device__ float g_Wp[3 * 16 * 64];
__device__ float g_bp[3 * 64];
__device__ float g_bnstats[128];
__device__ float g_bnscale[64];
__device__ float g_bnshift[64];
// packed tf32 hi/lo W fragments
__device__ float g_wpack[3 * 2 * 24 * 8 * 32 * 4];   // GRU: [l][which][nt24][ks8][lane][4]
__device__ float g_wlin[3 * 8 * 8 * 32 * 4];         // lin: [l][nt8][ks8][lane][4]
__device__ float g_wproj[8 * 16 * 32 * 4];           // proj: [nt8][ks16][lane][4]
// CSR by destination (col), with permuted payloads
__device__ int g_cntR[NN];
__device__ int g_cnt[NN];
__device__ int g_coff[NN + 1];
__device__ int g_cur[NN];
__device__ int g_bsum[128];
__device__ int g_erow[EE];
__device__ float g_nrm[EE];
__device__ float g_eattrp[EE * 16];

// ---------------- tf32 helpers ----------------
__device__ __forceinline__ unsigned f2tf32(float v) {
    unsigned r;
    asm("cvt.rna.tf32.f32 %0, %1;" : "=r"(r) : "f"(v));
    return r;
}
__device__ __forceinline__ void mma_tf32(float* c, unsigned a0, unsigned a1, unsigned a2,
                                         unsigned a3, unsigned b0, unsigned b1) {
    asm("mma.sync.aligned.m16n8k8.row.col.f32.tf32.tf32.f32 "
        "{%0,%1,%2,%3}, {%4,%5,%6,%7}, {%8,%9}, {%0,%1,%2,%3};"
        : "+f"(c[0]), "+f"(c[1]), "+f"(c[2]), "+f"(c[3])
        : "r"(a0), "r"(a1), "r"(a2), "r"(a3), "r"(b0), "r"(b1));
}

// shared mma core: As (pitch P), KT k-steps, N=64 out, 8 warps
template <int KT, int P>
__device__ __forceinline__ void mma_gemm_store(const float* As, const float* __restrict__ wpack,
                                               const float* __restrict__ bias,
                                               float* __restrict__ C, int M, int rowBase,
                                               int w, int lane) {
    const int mrow = w & 3;
    const int nhalf = w >> 2;
    const int g = lane >> 2, tg = lane & 3;
    float accs[4][4];
#pragma unroll
    for (int j = 0; j < 4; j++)
#pragma unroll
        for (int q = 0; q < 4; q++) accs[j][q] = 0.f;

#pragma unroll
    for (int ks = 0; ks < KT; ks++) {
        const int k0 = ks * 8;
        const float af[4] = {As[(mrow * 16 + g) * P + k0 + tg],
                             As[(mrow * 16 + g + 8) * P + k0 + tg],
                             As[(mrow * 16 + g) * P + k0 + tg + 4],
                             As[(mrow * 16 + g + 8) * P + k0 + tg + 4]};
        unsigned ah[4], al[4];
#pragma unroll
        for (int q = 0; q < 4; q++) {
            ah[q] = f2tf32(af[q]);
            al[q] = f2tf32(af[q] - __uint_as_float(ah[q]));
        }
#pragma unroll
        for (int j = 0; j < 4; j++) {
            const int nt = nhalf * 4 + j;
            const float4 b = __ldg(
                reinterpret_cast<const float4*>(&wpack[(((size_t)nt * KT + ks) * 32 + lane) * 4]));
            const unsigned bh0 = __float_as_uint(b.x);
            const unsigned bh4 = __float_as_uint(b.y);
            const unsigned bl0 = __float_as_uint(b.z);
            const unsigned bl4 = __float_as_uint(b.w);
            mma_tf32(accs[j], ah[0], ah[1], ah[2], ah[3], bh0, bh4);
            mma_tf32(accs[j], al[0], al[1], al[2], al[3], bh0, bh4);
            mma_tf32(accs[j], ah[0], ah[1], ah[2], ah[3], bl0, bl4);
        }
    }
#pragma unroll
    for (int j = 0; j < 4; j++) {
        const int n0 = (nhalf * 4 + j) * 8 + tg * 2;
        const float2 bv = make_float2(__ldg(&bias[n0]), __ldg(&bias[n0 + 1]));
        const int r0 = rowBase + mrow * 16 + g;
        if (r0 < M)
            *reinterpret_cast<float2*>(&C[(size_t)r0 * 64 + n0]) =
                make_float2(accs[j][0] + bv.x, accs[j][1] + bv.y);
        if (r0 + 8 < M)
            *reinterpret_cast<float2*>(&C[(size_t)(r0 + 8) * 64 + n0]) =
                make_float2(accs[j][2] + bv.x, accs[j][3] + bv.y);
    }
}

// ---------------- utility ----------------
__global__ void zero_kernel(float* __restrict__ p, int n) {
    int i = blockIdx.x * blockDim.x + threadIdx.x;
    int s = gridDim.x * blockDim.x;
    for (; i < n; i += s) p[i] = 0.f;
}
__global__ void zeroi_kernel(int* __restrict__ p, int n) {
    int i = blockIdx.x * blockDim.x + threadIdx.x;
    int s = gridDim.x * blockDim.x;
    for (; i < n; i += s) p[i] = 0;
}

// ---------------- pack GRU W hi/lo fragments ----------------
__global__ void packw_kernel(const float* __restrict__ Wih, const float* __restrict__ Whh) {
    const int l = blockIdx.x / 48;
    const int rem = blockIdx.x % 48;
    const int which = rem / 24;
    const int nt = rem % 24;
    const float* W = (which == 0 ? Wih : Whh) + (size_t)l * 192 * 64;
    const int ks = threadIdx.x >> 5;
    const int t = threadIdx.x & 31;
    const int g = t >> 2, tg = t & 3;
    const int n = nt * 8 + g;
    const int k0 = ks * 8 + tg;
    const float w0 = W[n * 64 + k0];
    const float w4 = W[n * 64 + k0 + 4];
    const unsigned h0 = f2tf32(w0), h4 = f2tf32(w4);
    float4 o;
    o.x = __uint_as_float(h0);
    o.y = __uint_as_float(h4);
    o.z = __uint_as_float(f2tf32(w0 - __uint_as_float(h0)));
    o.w = __uint_as_float(f2tf32(w4 - __uint_as_float(h4)));
    const size_t base = (((size_t)(l * 2 + which) * 24 + nt) * 8 + ks) * 32 + t;
    *reinterpret_cast<float4*>(&g_wpack[base * 4]) = o;
}

// ---------------- pack lin (3 layers, W transposed) ----------------
__global__ void packlin_kernel(const float* __restrict__ linW) {
    const int idx = blockIdx.x * 256 + threadIdx.x;  // 6144
    if (idx >= 3 * 8 * 8 * 32) return;
    const int l = idx / 2048;
    const int r1 = idx % 2048;
    const int nt = r1 / 256;
    const int r2 = r1 % 256;
    const int ks = r2 / 32;
    const int lane = r2 % 32;
    const int g = lane >> 2, tg = lane & 3;
    const int n = nt * 8 + g;
    const int k0 = ks * 8 + tg;
    const float* W = linW + (size_t)l * 4096;
    const float w0 = W[k0 * 64 + n];
    const float w4 = W[(k0 + 4) * 64 + n];
    const unsigned h0 = f2tf32(w0), h4 = f2tf32(w4);
    float4 o;
    o.x = __uint_as_float(h0);
    o.y = __uint_as_float(h4);
    o.z = __uint_as_float(f2tf32(w0 - __uint_as_float(h0)));
    o.w = __uint_as_float(f2tf32(w4 - __uint_as_float(h4)));
    *reinterpret_cast<float4*>(&g_wlin[(size_t)idx * 4]) = o;
}

// ---------------- pack proj (W transposed, K=128) ----------------
__global__ void packproj_kernel(const float* __restrict__ projW) {
    const int idx = blockIdx.x * 256 + threadIdx.x;  // 4096
    if (idx >= 8 * 16 * 32) return;
    const int nt = idx / 512;
    const int r = idx % 512;
    const int ks = r / 32;
    const int lane = r % 32;
    const int g = lane >> 2, tg = lane & 3;
    const int n = nt * 8 + g;
    const int k0 = ks * 8 + tg;
    const float w0 = projW[k0 * 64 + n];
    const float w4 = projW[(k0 + 4) * 64 + n];
    const unsigned h0 = f2tf32(w0), h4 = f2tf32(w4);
    float4 o;
    o.x = __uint_as_float(h0);
    o.y = __uint_as_float(h4);
    o.z = __uint_as_float(f2tf32(w0 - __uint_as_float(h0)));
    o.w = __uint_as_float(f2tf32(w4 - __uint_as_float(h4)));
    *reinterpret_cast<float4*>(&g_wproj[(size_t)idx * 4]) = o;
}

// ---------------- combined degree(row) + count(col) ----------------
__global__ void count_kernel(const int* __restrict__ rowI, const int* __restrict__ colI) {
    int s = gridDim.x * blockDim.x;
    for (int e = blockIdx.x * blockDim.x + threadIdx.x; e < EE; e += s) {
        atomicAdd(&g_cntR[rowI[e]], 1);
        atomicAdd(&g_cnt[colI[e]], 1);
    }
}
__global__ void finalize_deg_kernel() {
    int s = gridDim.x * blockDim.x;
    for (int n = blockIdx.x * blockDim.x + threadIdx.x; n < NN; n += s) {
        float dv = (float)g_cntR[n] + 1.f;
        g_deg[n] = dv;
        g_dinv[n] = rsqrtf(dv);
    }
}

// ---------------- CSR scan ----------------
__global__ void __launch_bounds__(256) scan1_kernel() {
    __shared__ int wsum[8];
    const int b = blockIdx.x;
    const int base = b * 1024;
    const int t = threadIdx.x;
    const int lane = t & 31, w = t >> 5;
    int v[4];
    const int idx0 = base + t * 4;
#pragma unroll
    for (int i = 0; i < 4; i++) {
        const int ii = idx0 + i;
        v[i] = (ii < NN) ? g_cnt[ii] : 0;
    }
    const int local = v[0] + v[1] + v[2] + v[3];
    int x = local;
#pragma unroll
    for (int off = 1; off < 32; off <<= 1) {
        int y = __shfl_up_sync(0xffffffffu, x, off);
        if (lane >= off) x += y;
    }
    if (lane == 31) wsum[w] = x;
    __syncthreads();
    if (t == 0) {
        int s = 0;
#pragma unroll
        for (int i = 0; i < 8; i++) { int tmp = wsum[i]; wsum[i] = s; s += tmp; }
        g_bsum[b] = s;
    }
    __syncthreads();
    int run = x - local + wsum[w];
#pragma unroll
    for (int i = 0; i < 4; i++) {
        const int ii = idx0 + i;
        if (ii < NN) g_coff[ii] = run;
        run += v[i];
    }
}
__global__ void scan2_kernel(int nb) {
    if (threadIdx.x == 0 && blockIdx.x == 0) {
        int s = 0;
        for (int i = 0; i < nb; i++) { int t = g_bsum[i]; g_bsum[i] = s; s += t; }
    }
}
__global__ void scan3_kernel() {
    int i = blockIdx.x * blockDim.x + threadIdx.x;
    int s = gridDim.x * blockDim.x;
    for (; i < NN; i += s) {
        const int vv = g_coff[i] + g_bsum[i >> 10];
        g_coff[i] = vv;
        g_cur[i] = vv;
    }
    if (blockIdx.x == 0 && threadIdx.x == 0) g_coff[NN] = EE;
}

// ---------------- fill: permute payloads into CSR order ----------------
__global__ void fill_kernel(const int* __restrict__ rowI, const int* __restrict__ colI,
                            const float* __restrict__ eattr) {
    int s = gridDim.x * blockDim.x;
    for (int e = blockIdx.x * blockDim.x + threadIdx.x; e < EE; e += s) {
        const int c = colI[e];
        const int r = rowI[e];
        const int pos = atomicAdd(&g_cur[c], 1);
        g_erow[pos] = r;
        g_nrm[pos] = g_dinv[r] * g_dinv[c];
        const float4* src = reinterpret_cast<const float4*>(eattr + (size_t)e * 16);
        float4* dst = reinterpret_cast<float4*>(g_eattrp + (size_t)pos * 16);
        dst[0] = __ldg(&src[0]);
        dst[1] = __ldg(&src[1]);
        dst[2] = __ldg(&src[2]);
        dst[3] = __ldg(&src[3]);
    }
}

// ---------------- edge-attr second-moment stats ----------------
__global__ void __launch_bounds__(256) stats_kernel(const float* __restrict__ eattr) {
    const int tid = threadIdx.x;
    const int parity = tid & 1;
    const int pair0 = (blockIdx.x * 256 + tid) >> 1;
    const int npairs = (gridDim.x * 256) >> 1;
    float sAcc[68];
    float mAcc[8];
#pragma unroll
    for (int i = 0; i < 68; i++) sAcc[i] = 0.f;
#pragma unroll
    for (int i = 0; i < 8; i++) mAcc[i] = 0.f;

    for (int e = pair0; e < EE; e += npairs) {
        const float4* ap = reinterpret_cast<const float4*>(eattr + (size_t)e * 16);
        float4 v0 = __ldg(&ap[0]), v1 = __ldg(&ap[1]), v2 = __ldg(&ap[2]), v3 = __ldg(&ap[3]);
        float a[16];
        a[0]=v0.x; a[1]=v0.y; a[2]=v0.z; a[3]=v0.w;
        a[4]=v1.x; a[5]=v1.y; a[6]=v1.z; a[7]=v1.w;
        a[8]=v2.x; a[9]=v2.y; a[10]=v2.z; a[11]=v2.w;
        a[12]=v3.x; a[13]=v3.y; a[14]=v3.z; a[15]=v3.w;
#pragma unroll
        for (int i = 0; i < 16; i++)
            if ((i >> 3) == parity) mAcc[i & 7] += a[i];
        int p = 0;
#pragma unroll
        for (int k = 0; k < 16; k++)
#pragma unroll
            for (int l = k; l < 16; l++) {
                if ((p & 1) == parity) sAcc[p >> 1] += a[k] * a[l];
                p++;
            }
    }
#pragma unroll
    for (int off = 16; off >= 2; off >>= 1) {
#pragma unroll
        for (int i = 0; i < 68; i++) sAcc[i] += __shfl_down_sync(0xffffffffu, sAcc[i], off);
#pragma unroll
        for (int i = 0; i < 8; i++) mAcc[i] += __shfl_down_sync(0xffffffffu, mAcc[i], off);
    }
    const int lane = tid & 31;
    if (lane < 2) {
#pragma unroll
        for (int i = 0; i < 68; i++) atomicAdd(&g_stats[i * 2 + lane], sAcc[i]);
#pragma unroll
        for (int i = 0; i < 8; i++) atomicAdd(&g_stats[136 + lane * 8 + i], mAcc[i]);
    }
}

// ---------------- fold bond Linear+BN into W', b' (blockIdx = layer) ----------------
__global__ void bondprep_kernel(const float* __restrict__ bondW, const float* __restrict__ bondb,
                                const float* __restrict__ bondg,
                                const float* __restrict__ bondbeta) {
    const int l = blockIdx.x;
    const int j = threadIdx.x;
    const float* Wl = bondW + (size_t)l * 16 * 64;
    const float invE = 1.f / (float)EE;
    float w[16];
#pragma unroll
    for (int k = 0; k < 16; k++) w[k] = Wl[k * 64 + j];
    float dot_mw = 0.f;
#pragma unroll
    for (int k = 0; k < 16; k++) dot_mw += (g_stats[136 + k] * invE) * w[k];
    float quad = 0.f;
    int p = 0;
#pragma unroll
    for (int k = 0; k < 16; k++)
#pragma unroll
        for (int l2 = k; l2 < 16; l2++) {
            const float s = g_stats[p++] * invE;
            quad += (k == l2 ? w[k] * w[l2] : 2.f * w[k] * w[l2]) * s;
        }
    const float b = bondb[l * 64 + j];
    const float mean = dot_mw + b;
    const float e2 = quad + 2.f * b * dot_mw + b * b;
    const float var = e2 - mean * mean;
    const float scale = bondg[l * 64 + j] * rsqrtf(var + 1e-6f);
#pragma unroll
    for (int k = 0; k < 16; k++) g_Wp[l * 1024 + k * 64 + j] = w[k] * scale;
    g_bp[l * 64 + j] = (b - mean) * scale + bondbeta[l * 64 + j];
}

// ---------------- proj GEMM with fused atom encoder (tf32 mma) ----------------
__global__ void __launch_bounds__(256) proj_mma_kernel(const float* __restrict__ ax,
                                                       const int* __restrict__ feat,
                                                       const float* __restrict__ emb,
                                                       const float* __restrict__ bias, int M) {
    __shared__ float As[64 * 132];
    const int tid = threadIdx.x;
    const int rowBase = blockIdx.x * 64;
#pragma unroll
    for (int idx = tid; idx < 64 * 32; idx += 256) {
        const int r = idx >> 5;
        const int c4 = idx & 31;
        const int gr = rowBase + r;
        float4 v = make_float4(0.f, 0.f, 0.f, 0.f);
        if (gr < M) {
            if (c4 < 16) {
                v = __ldg(reinterpret_cast<const float4*>(&ax[(size_t)gr * 64 + c4 * 4]));
            } else {
                const int d = (c4 - 16) * 4;
#pragma unroll
                for (int f = 0; f < 9; f++) {
                    const int fv = __ldg(&feat[gr * 9 + f]);
                    const float4 ev =
                        __ldg(reinterpret_cast<const float4*>(&emb[(f * 16 + fv) * 64 + d]));
                    v.x += ev.x; v.y += ev.y; v.z += ev.z; v.w += ev.w;
                }
            }
        }
        *reinterpret_cast<float4*>(&As[r * 132 + c4 * 4]) = v;
    }
    __syncthreads();
    mma_gemm_store<16, 132>(As, g_wproj, bias, g_h, M, rowBase, tid >> 5, tid & 31);
}

// ---------------- lin GEMM (tf32 mma), optional fused BN+relu on A ----------------
template <int MODE>  // 0 plain, 1 BN(scale/shift)+relu
__global__ void __launch_bounds__(256) lin_mma_kernel(const float* __restrict__ H,
                                                      const float* __restrict__ wpack,
                                                      const float* __restrict__ bias, int M) {
    __shared__ float As[64 * 68];
    const int tid = threadIdx.x;
    const int rowBase = blockIdx.x * 64;
#pragma unroll
    for (int idx = tid; idx < 64 * 16; idx += 256) {
        const int r = idx >> 4;
        const int c4 = idx & 15;
        const int gr = rowBase + r;
        float4 v = make_float4(0.f, 0.f, 0.f, 0.f);
        if (gr < M) {
            v = *reinterpret_cast<const float4*>(&H[(size_t)gr * 64 + c4 * 4]);
            if (MODE == 1) {
                const int d = c4 * 4;
                v.x = fmaxf(v.x * g_bnscale[d + 0] + g_bnshift[d + 0], 0.f);
                v.y = fmaxf(v.y * g_bnscale[d + 1] + g_bnshift[d + 1], 0.f);
                v.z = fmaxf(v.z * g_bnscale[d + 2] + g_bnshift[d + 2], 0.f);
                v.w = fmaxf(v.w * g_bnscale[d + 3] + g_bnshift[d + 3], 0.f);
            }
        }
        *reinterpret_cast<float4*>(&As[r * 68 + c4 * 4]) = v;
    }
    __syncthreads();
    mma_gemm_store<8, 68>(As, wpack, bias, g_x, M, rowBase, tid >> 5, tid & 31);
}

// ---------------- CSR gather (16 thr/node, float4, W' in regs; edge loop unroll-2) -------
__global__ void __launch_bounds__(256) gather_kernel(int layer) {
    const int tid = threadIdx.x;
    const int t = tid & 15;
    const int nloc = tid >> 4;
    const int n = blockIdx.x * 16 + nloc;
    const float* Wp = g_Wp + layer * 1024;
    const float* bp = g_bp + layer * 64;
    float4 wreg[16];
#pragma unroll
    for (int k = 0; k < 16; k++)
        wreg[k] = *reinterpret_cast<const float4*>(&Wp[k * 64 + t * 4]);
    const float4 bb = *reinterpret_cast<const float4*>(&bp[t * 4]);
    if (n >= NN) return;
    const int jb = g_coff[n];
    const int je = g_coff[n + 1];
    float4 acc = make_float4(0.f, 0.f, 0.f, 0.f);
    int j = jb;
#pragma unroll 1
    for (; j + 2 <= je; j += 2) {
        const int r0 = __ldg(&g_erow[j]);
        const int r1 = __ldg(&g_erow[j + 1]);
        const float nrm0 = __ldg(&g_nrm[j]);
        const float nrm1 = __ldg(&g_nrm[j + 1]);
        const float4* ap0 = reinterpret_cast<const float4*>(g_eattrp + (size_t)j * 16);
        const float4* ap1 = reinterpret_cast<const float4*>(g_eattrp + (size_t)(j + 1) * 16);
        float4 m0 = bb, m1 = bb;
#pragma unroll
        for (int q = 0; q < 4; q++) {
            const float4 a0 = __ldg(&ap0[q]);
            const float4 a1 = __ldg(&ap1[q]);
            const float4 w0 = wreg[4 * q + 0];
            const float4 w1 = wreg[4 * q + 1];
            const float4 w2 = wreg[4 * q + 2];
            const float4 w3 = wreg[4 * q + 3];
            m0.x = fmaf(a0.x, w0.x, fmaf(a0.y, w1.x, fmaf(a0.z, w2.x, fmaf(a0.w, w3.x, m0.x))));
            m0.y = fmaf(a0.x, w0.y, fmaf(a0.y, w1.y, fmaf(a0.z, w2.y, fmaf(a0.w, w3.y, m0.y))));
            m0.z = fmaf(a0.x, w0.z, fmaf(a0.y, w1.z, fmaf(a0.z, w2.z, fmaf(a0.w, w3.z, m0.z))));
            m0.w = fmaf(a0.x, w0.w, fmaf(a0.y, w1.w, fmaf(a0.z, w2.w, fmaf(a0.w, w3.w, m0.w))));
            m1.x = fmaf(a1.x, w0.x, fmaf(a1.y, w1.x, fmaf(a1.z, w2.x, fmaf(a1.w, w3.x, m1.x))));
            m1.y = fmaf(a1.x, w0.y, fmaf(a1.y, w1.y, fmaf(a1.z, w2.y, fmaf(a1.w, w3.y, m1.y))));
            m1.z = fmaf(a1.x, w0.z, fmaf(a1.y, w1.z, fmaf(a1.z, w2.z, fmaf(a1.w, w3.z, m1.z))));
            m1.w = fmaf(a1.x, w0.w, fmaf(a1.y, w1.w, fmaf(a1.z, w2.w, fmaf(a1.w, w3.w, m1.w))));
        }
        const float4 x0 = __ldg(reinterpret_cast<const float4*>(&g_x[(size_t)r0 * 64 + t * 4]));
        const float4 x1 = __ldg(reinterpret_cast<const float4*>(&g_x[(size_t)r1 * 64 + t * 4]));
        acc.x = fmaf(nrm0, fmaxf(m0.x + x0.x, 0.f), acc.x);
        acc.y = fmaf(nrm0, fmaxf(m0.y + x0.y, 0.f), acc.y);
        acc.z = fmaf(nrm0, fmaxf(m0.z + x0.z, 0.f), acc.z);
        acc.w = fmaf(nrm0, fmaxf(m0.w + x0.w, 0.f), acc.w);
        acc.x = fmaf(nrm1, fmaxf(m1.x + x1.x, 0.f), acc.x);
        acc.y = fmaf(nrm1, fmaxf(m1.y + x1.y, 0.f), acc.y);
        acc.z = fmaf(nrm1, fmaxf(m1.z + x1.z, 0.f), acc.z);
        acc.w = fmaf(nrm1, fmaxf(m1.w + x1.w, 0.f), acc.w);
    }
    if (j < je) {
        const int r = __ldg(&g_erow[j]);
        const float nrm = __ldg(&g_nrm[j]);
        const float4* ap = reinterpret_cast<const float4*>(g_eattrp + (size_t)j * 16);
        float4 m = bb;
#pragma unroll
        for (int q = 0; q < 4; q++) {
            const float4 a = __ldg(&ap[q]);
            const float4 w0 = wreg[4 * q + 0];
            const float4 w1 = wreg[4 * q + 1];
            const float4 w2 = wreg[4 * q + 2];
            const float4 w3 = wreg[4 * q + 3];
            m.x = fmaf(a.x, w0.x, fmaf(a.y, w1.x, fmaf(a.z, w2.x, fmaf(a.w, w3.x, m.x))));
            m.y = fmaf(a.x, w0.y, fmaf(a.y, w1.y, fmaf(a.z, w2.y, fmaf(a.w, w3.y, m.y))));
            m.z = fmaf(a.x, w0.z, fmaf(a.y, w1.z, fmaf(a.z, w2.z, fmaf(a.w, w3.z, m.z))));
            m.w = fmaf(a.x, w0.w, fmaf(a.y, w1.w, fmaf(a.z, w2.w, fmaf(a.w, w3.w, m.w))));
        }
        const float4 xv = __ldg(reinterpret_cast<const float4*>(&g_x[(size_t)r * 64 + t * 4]));
        acc.x = fmaf(nrm, fmaxf(m.x + xv.x, 0.f), acc.x);
        acc.y = fmaf(nrm, fmaxf(m.y + xv.y, 0.f), acc.y);
        acc.z = fmaf(nrm, fmaxf(m.z + xv.z, 0.f), acc.z);
        acc.w = fmaf(nrm, fmaxf(m.w + xv.w, 0.f), acc.w);
    }
    *reinterpret_cast<float4*>(&g_aggr[(size_t)n * 64 + t * 4]) = acc;
}

// ---------------- fused GRU with tf32 HMMA (3xTF32) ----------------
__global__ void __launch_bounds__(256, 1) grumma_kernel(
    const float* __restrict__ bih, const float* __restrict__ bhh,
    const float* __restrict__ root, const float* __restrict__ wpackI,
    const float* __restrict__ wpackH, int M) {
    extern __shared__ float smem[];
    float* Aag = smem;
    float* Ax = Aag + 64 * 68;
    float* Sgi = Ax + 64 * 68;
    float* Sgh = Sgi + 64 * 196;
    float* ssum = Sgh + 64 * 196;
    float* ssq = ssum + 64;

    const int tid = threadIdx.x;
    const int w = tid >> 5;
    const int lane = tid & 31;
    const int rowBase = blockIdx.x * 64;

#pragma unroll
    for (int idx = tid; idx < 64 * 16; idx += 256) {
        const int r = idx >> 4;
        const int c4 = idx & 15;
        const int gr = rowBase + r;
        float4 va = make_float4(0.f, 0.f, 0.f, 0.f);
        float4 vx = make_float4(0.f, 0.f, 0.f, 0.f);
        if (gr < M) {
            va = *reinterpret_cast<const float4*>(&g_aggr[(size_t)gr * 64 + c4 * 4]);
            vx = *reinterpret_cast<const float4*>(&g_x[(size_t)gr * 64 + c4 * 4]);
        }
        *reinterpret_cast<float4*>(&Aag[r * 68 + c4 * 4]) = va;
        *reinterpret_cast<float4*>(&Ax[r * 68 + c4 * 4]) = vx;
    }
    if (tid < 64) { ssum[tid] = 0.f; ssq[tid] = 0.f; }
    __syncthreads();

    const int mrow = w & 3;
    const int ntbase = (w >> 2) * 12;
    const int g = lane >> 2, tg = lane & 3;

#pragma unroll
    for (int which = 0; which < 2; which++) {
        const float* A = (which == 0) ? Aag : Ax;
        const float* wp = (which == 0) ? wpackI : wpackH;
        float* S = (which == 0) ? Sgi : Sgh;

        float accs[12][4];
#pragma unroll
        for (int j = 0; j < 12; j++)
#pragma unroll
            for (int q = 0; q < 4; q++) accs[j][q] = 0.f;

#pragma unroll
        for (int ks = 0; ks < 8; ks++) {
            const int k0 = ks * 8;
            const float af[4] = {A[(mrow * 16 + g) * 68 + k0 + tg],
                                 A[(mrow * 16 + g + 8) * 68 + k0 + tg],
                                 A[(mrow * 16 + g) * 68 + k0 + tg + 4],
                                 A[(mrow * 16 + g + 8) * 68 + k0 + tg + 4]};
            unsigned ah[4], al[4];
#pragma unroll
            for (int q = 0; q < 4; q++) {
                ah[q] = f2tf32(af[q]);
                al[q] = f2tf32(af[q] - __uint_as_float(ah[q]));
            }
#pragma unroll
            for (int j = 0; j < 12; j++) {
                const int nt = ntbase + j;
                const float4 b =
                    __ldg(reinterpret_cast<const float4*>(&wp[(((size_t)nt * 8 + ks) * 32 + lane) * 4]));
                const unsigned bh0 = __float_as_uint(b.x);
                const unsigned bh4 = __float_as_uint(b.y);
                const unsigned bl0 = __float_as_uint(b.z);
                const unsigned bl4 = __float_as_uint(b.w);
                mma_tf32(accs[j], ah[0], ah[1], ah[2], ah[3], bh0, bh4);
                mma_tf32(accs[j], al[0], al[1], al[2], al[3], bh0, bh4);
                mma_tf32(accs[j], ah[0], ah[1], ah[2], ah[3], bl0, bl4);
            }
        }
#pragma unroll
        for (int j = 0; j < 12; j++) {
            const int n0 = (ntbase + j) * 8;
            const int r0 = mrow * 16 + g;
            *reinterpret_cast<float2*>(&S[r0 * 196 + n0 + tg * 2]) =
                make_float2(accs[j][0], accs[j][1]);
            *reinterpret_cast<float2*>(&S[(r0 + 8) * 196 + n0 + tg * 2]) =
                make_float2(accs[j][2], accs[j][3]);
        }
    }
    __syncthreads();

    const int tx = tid & 15;
    const int ty = tid >> 4;
    float ls[4] = {0.f, 0.f, 0.f, 0.f};
    float ls2[4] = {0.f, 0.f, 0.f, 0.f};
#pragma unroll
    for (int ri = 0; ri < 4; ri++) {
        const int r = ty * 4 + ri;
        const int row = rowBase + r;
        if (row < M) {
            const float dg = __ldg(&g_deg[row]);
#pragma unroll
            for (int di = 0; di < 4; di++) {
                const int d = di * 16 + tx;
                const float ir = Sgi[r * 196 + d] + __ldg(&bih[d]);
                const float iz = Sgi[r * 196 + 64 + d] + __ldg(&bih[64 + d]);
                const float inn = Sgi[r * 196 + 128 + d] + __ldg(&bih[128 + d]);
                const float hr = Sgh[r * 196 + d] + __ldg(&bhh[d]);
                const float hz = Sgh[r * 196 + 64 + d] + __ldg(&bhh[64 + d]);
                const float hn = Sgh[r * 196 + 128 + d] + __ldg(&bhh[128 + d]);
                const float xv = Ax[r * 68 + d];
                const float rr = 1.f / (1.f + expf(-(ir + hr)));
                const float z = 1.f / (1.f + expf(-(iz + hz)));
                const float nn2 = tanhf(inn + rr * hn);
                const float upd = (1.f - z) * nn2 + z * xv;
                const float hl = upd + fmaxf(xv + __ldg(&root[d]), 0.f) / dg;
                g_h[(size_t)row * 64 + d] = hl;
                ls[di] += hl;
                ls2[di] += hl * hl;
            }
        }
    }
#pragma unroll
    for (int di = 0; di < 4; di++) {
        atomicAdd(&ssum[di * 16 + tx], ls[di]);
        atomicAdd(&ssq[di * 16 + tx], ls2[di]);
    }
    __syncthreads();
    if (tid < 64) {
        atomicAdd(&g_bnstats[tid], ssum[tid]);
        atomicAdd(&g_bnstats[64 + tid], ssq[tid]);
    }
}

// ---------------- finalize BN stats -> scale/shift ----------------
__global__ void bnfin_kernel(const float* __restrict__ gamma, const float* __restrict__ beta) {
    const int d = threadIdx.x;  // 64
    const float invN = 1.f / (float)NN;
    const float mean = g_bnstats[d] * invN;
    const float var = g_bnstats[64 + d] * invN - mean * mean;
    const float sc = gamma[d] * rsqrtf(var + 1e-5f);
    g_bnscale[d] = sc;
    g_bnshift[d] = beta[d] - mean * sc;
}

// ---------------- final output: BN apply (no relu) ----------------
__global__ void __launch_bounds__(256) bnout_kernel(float* __restrict__ out) {
    const int start = blockIdx.x * 256 + threadIdx.x;
    const int stride = gridDim.x * 256;
    for (int idx = start; idx < NN * 64; idx += stride) {
        const int d = idx & 63;
        out[idx] = g_h[idx] * g_bnscale[d] + g_bnshift[d];
    }
}

// ---------------- launch (3-stream fork/join) ----------------
extern "C" void kernel_launch(void* const* d_in, const int* in_sizes, int n_in,
                              void* d_out, int out_size) {
    const float* atom_x = (const float*)d_in[0];
    const int* atom_feature = (const int*)d_in[1];
    const int* edge_index = (const int*)d_in[2];
    const float* edge_attr = (const float*)d_in[3];
    const float* atom_emb = (const float*)d_in[4];
    const float* proj_W = (const float*)d_in[5];
    const float* proj_b = (const float*)d_in[6];
    const float* lin_W = (const float*)d_in[7];
    const float* lin_b = (const float*)d_in[8];
    const float* root_emb = (const float*)d_in[9];
    const float* bond_W = (const float*)d_in[10];
    const float* bond_b = (const float*)d_in[11];
    const float* bond_g = (const float*)d_in[12];
    const float* bond_beta = (const float*)d_in[13];
    const float* gru_Wih = (const float*)d_in[14];
    const float* gru_bih = (const float*)d_in[15];
    const float* gru_Whh = (const float*)d_in[16];
    const float* gru_bhh = (const float*)d_in[17];
    const float* bn_g = (const float*)d_in[18];
    const float* bn_b = (const float*)d_in[19];
    const int* rowI = edge_index;
    const int* colI = edge_index + EE;
    float* out = (float*)d_out;

    float *p_h, *p_stats, *p_bnstats, *p_wpack, *p_wlin;
    int *p_cnt, *p_cntR;
    cudaGetSymbolAddress((void**)&p_h, g_h);
    cudaGetSymbolAddress((void**)&p_stats, g_stats);
    cudaGetSymbolAddress((void**)&p_bnstats, g_bnstats);
    cudaGetSymbolAddress((void**)&p_cnt, g_cnt);
    cudaGetSymbolAddress((void**)&p_cntR, g_cntR);
    cudaGetSymbolAddress((void**)&p_wpack, g_wpack);
    cudaGetSymbolAddress((void**)&p_wlin, g_wlin);

    static cudaStream_t st1 = nullptr, st2 = nullptr;
    static cudaEvent_t evFork = nullptr, evJ1 = nullptr, evJ2 = nullptr;
    static int inited = 0;
    const int gruSmem = (2 * 64 * 68 + 2 * 64 * 196 + 128) * 4;
    if (!inited) {
        cudaFuncSetAttribute(grumma_kernel, cudaFuncAttributeMaxDynamicSharedMemorySize,
                             gruSmem);
        cudaStreamCreateWithFlags(&st1, cudaStreamNonBlocking);
        cudaStreamCreateWithFlags(&st2, cudaStreamNonBlocking);
        cudaEventCreateWithFlags(&evFork, cudaEventDisableTiming);
        cudaEventCreateWithFlags(&evJ1, cudaEventDisableTiming);
        cudaEventCreateWithFlags(&evJ2, cudaEventDisableTiming);
        inited = 1;
    }

    const int nScanBlocks = (NN + 1023) / 1024;

    // fork point (no prior work on default stream this launch)
    cudaEventRecord(evFork, 0);
    cudaStreamWaitEvent(st1, evFork, 0);
    cudaStreamWaitEvent(st2, evFork, 0);

    // stream 0: CSR chain
    zeroi_kernel<<<256, 256>>>(p_cnt, NN);
    zeroi_kernel<<<256, 256>>>(p_cntR, NN);
    count_kernel<<<1024, 256>>>(rowI, colI);
    finalize_deg_kernel<<<256, 256>>>();
    scan1_kernel<<<nScanBlocks, 256>>>();
    scan2_kernel<<<1, 32>>>(nScanBlocks);
    scan3_kernel<<<256, 256>>>();
    fill_kernel<<<1024, 256>>>(rowI, colI, edge_attr);

    // stream 1: stats -> all 3 bondpreps
    zero_kernel<<<1, 256, 0, st1>>>(p_stats, 152);
    stats_kernel<<<296, 256, 0, st1>>>(edge_attr);
    bondprep_kernel<<<3, 64, 0, st1>>>(bond_W, bond_b, bond_g, bond_beta);
    cudaEventRecord(evJ1, st1);

    // stream 2: packs -> proj -> lin0
    packw_kernel<<<144, 256, 0, st2>>>(gru_Wih, gru_Whh);
    packlin_kernel<<<24, 256, 0, st2>>>(lin_W);
    packproj_kernel<<<16, 256, 0, st2>>>(proj_W);
    proj_mma_kernel<<<1563, 256, 0, st2>>>(atom_x, atom_feature, atom_emb, proj_b, NN);
    lin_mma_kernel<0><<<1563, 256, 0, st2>>>(p_h, p_wlin, lin_b, NN);
    cudaEventRecord(evJ2, st2);

    // join on default stream
    cudaStreamWaitEvent(0, evJ1, 0);
    cudaStreamWaitEvent(0, evJ2, 0);

    for (int l = 0; l < 3; l++) {
        if (l > 0)
            lin_mma_kernel<1><<<1563, 256>>>(p_h, p_wlin + (size_t)l * 8192, lin_b + l * 64, NN);
        gather_kernel<<<(NN + 15) / 16, 256>>>(l);
        zero_kernel<<<1, 128>>>(p_bnstats, 128);
        grumma_kernel<<<1563, 256, gruSmem>>>(gru_bih + l * 192, gru_bhh + l * 192,
                                              root_emb + l * 64,
                                              p_wpack + (size_t)(l * 2 + 0) * 24576,
                                              p_wpack + (size_t)(l * 2 + 1) * 24576, NN);
        bnfin_kernel<<<1, 64>>>(bn_g + l * 64, bn_b + l * 64);
    }
    bnout_kernel<<<512, 256>>>(out);
}

// round 16
// speedup vs baseline: 1.4502x; 1.4502x over previous
#include <cuda_runtime.h>
#include <math.h>

#define NN 100000
#define EE 1600000

// ---------------- scratch (device globals) ----------------
__device__ float g_h[NN * 64];
__device__ float g_x[NN * 64];
__device__ float g_aggr[NN * 64];
__device__ float g_deg[NN];
__device__ float g_dinv[NN];
__device__ float g_stats[152];
__device__ float g_Wp[16 * 64];
__device__ float g_bp[64];
__device__ float g_bnstats[128];
__device__ float g_bnscale[64];
__device__ float g_bnshift[64];
// packed tf32 hi/lo W fragments
__device__ float g_wpack[3 * 2 * 24 * 8 * 32 * 4];   // GRU: [l][which][nt24][ks8][lane][4]
__device__ float g_wlin[3 * 8 * 8 * 32 * 4];         // lin: [l][nt8][ks8][lane][4]
__device__ float g_wproj[8 * 16 * 32 * 4];           // proj: [nt8][ks16][lane][4]
// CSR by destination (col), with permuted payloads
__device__ int g_cntR[NN];
__device__ int g_cnt[NN];
__device__ int g_coff[NN + 1];
__device__ int g_cur[NN];
__device__ int g_bsum[128];
__device__ int g_erow[EE];
__device__ float g_nrm[EE];
__device__ float g_eattrp[EE * 16];

// ---------------- tf32 helpers ----------------
__device__ __forceinline__ unsigned f2tf32(float v) {
    unsigned r;
    asm("cvt.rna.tf32.f32 %0, %1;" : "=r"(r) : "f"(v));
    return r;
}
__device__ __forceinline__ void mma_tf32(float* c, unsigned a0, unsigned a1, unsigned a2,
                                         unsigned a3, unsigned b0, unsigned b1) {
    asm("mma.sync.aligned.m16n8k8.row.col.f32.tf32.tf32.f32 "
        "{%0,%1,%2,%3}, {%4,%5,%6,%7}, {%8,%9}, {%0,%1,%2,%3};"
        : "+f"(c[0]), "+f"(c[1]), "+f"(c[2]), "+f"(c[3])
        : "r"(a0), "r"(a1), "r"(a2), "r"(a3), "r"(b0), "r"(b1));
}

// shared mma core: As (pitch P), KT k-steps, N=64 out, 8 warps
template <int KT, int P>
__device__ __forceinline__ void mma_gemm_store(const float* As, const float* __restrict__ wpack,
                                               const float* __restrict__ bias,
                                               float* __restrict__ C, int M, int rowBase,
                                               int w, int lane) {
    const int mrow = w & 3;
    const int nhalf = w >> 2;
    const int g = lane >> 2, tg = lane & 3;
    float accs[4][4];
#pragma unroll
    for (int j = 0; j < 4; j++)
#pragma unroll
        for (int q = 0; q < 4; q++) accs[j][q] = 0.f;

#pragma unroll
    for (int ks = 0; ks < KT; ks++) {
        const int k0 = ks * 8;
        const float af[4] = {As[(mrow * 16 + g) * P + k0 + tg],
                             As[(mrow * 16 + g + 8) * P + k0 + tg],
                             As[(mrow * 16 + g) * P + k0 + tg + 4],
                             As[(mrow * 16 + g + 8) * P + k0 + tg + 4]};
        unsigned ah[4], al[4];
#pragma unroll
        for (int q = 0; q < 4; q++) {
            ah[q] = f2tf32(af[q]);
            al[q] = f2tf32(af[q] - __uint_as_float(ah[q]));
        }
#pragma unroll
        for (int j = 0; j < 4; j++) {
            const int nt = nhalf * 4 + j;
            const float4 b = __ldg(
                reinterpret_cast<const float4*>(&wpack[(((size_t)nt * KT + ks) * 32 + lane) * 4]));
            const unsigned bh0 = __float_as_uint(b.x);
            const unsigned bh4 = __float_as_uint(b.y);
            const unsigned bl0 = __float_as_uint(b.z);
            const unsigned bl4 = __float_as_uint(b.w);
            mma_tf32(accs[j], ah[0], ah[1], ah[2], ah[3], bh0, bh4);
            mma_tf32(accs[j], al[0], al[1], al[2], al[3], bh0, bh4);
            mma_tf32(accs[j], ah[0], ah[1], ah[2], ah[3], bl0, bl4);
        }
    }
#pragma unroll
    for (int j = 0; j < 4; j++) {
        const int n0 = (nhalf * 4 + j) * 8 + tg * 2;
        const float2 bv = make_float2(__ldg(&bias[n0]), __ldg(&bias[n0 + 1]));
        const int r0 = rowBase + mrow * 16 + g;
        if (r0 < M)
            *reinterpret_cast<float2*>(&C[(size_t)r0 * 64 + n0]) =
                make_float2(accs[j][0] + bv.x, accs[j][1] + bv.y);
        if (r0 + 8 < M)
            *reinterpret_cast<float2*>(&C[(size_t)(r0 + 8) * 64 + n0]) =
                make_float2(accs[j][2] + bv.x, accs[j][3] + bv.y);
    }
}

// ---------------- utility ----------------
__global__ void zero_kernel(float* __restrict__ p, int n) {
    int i = blockIdx.x * blockDim.x + threadIdx.x;
    int s = gridDim.x * blockDim.x;
    for (; i < n; i += s) p[i] = 0.f;
}
__global__ void zeroi_kernel(int* __restrict__ p, int n) {
    int i = blockIdx.x * blockDim.x + threadIdx.x;
    int s = gridDim.x * blockDim.x;
    for (; i < n; i += s) p[i] = 0;
}

// ---------------- pack GRU W hi/lo fragments ----------------
__global__ void packw_kernel(const float* __restrict__ Wih, const float* __restrict__ Whh) {
    const int l = blockIdx.x / 48;
    const int rem = blockIdx.x % 48;
    const int which = rem / 24;
    const int nt = rem % 24;
    const float* W = (which == 0 ? Wih : Whh) + (size_t)l * 192 * 64;
    const int ks = threadIdx.x >> 5;
    const int t = threadIdx.x & 31;
    const int g = t >> 2, tg = t & 3;
    const int n = nt * 8 + g;
    const int k0 = ks * 8 + tg;
    const float w0 = W[n * 64 + k0];
    const float w4 = W[n * 64 + k0 + 4];
    const unsigned h0 = f2tf32(w0), h4 = f2tf32(w4);
    float4 o;
    o.x = __uint_as_float(h0);
    o.y = __uint_as_float(h4);
    o.z = __uint_as_float(f2tf32(w0 - __uint_as_float(h0)));
    o.w = __uint_as_float(f2tf32(w4 - __uint_as_float(h4)));
    const size_t base = (((size_t)(l * 2 + which) * 24 + nt) * 8 + ks) * 32 + t;
    *reinterpret_cast<float4*>(&g_wpack[base * 4]) = o;
}

// ---------------- pack lin (3 layers, W transposed) ----------------
__global__ void packlin_kernel(const float* __restrict__ linW) {
    const int idx = blockIdx.x * 256 + threadIdx.x;  // 6144
    if (idx >= 3 * 8 * 8 * 32) return;
    const int l = idx / 2048;
    const int r1 = idx % 2048;
    const int nt = r1 / 256;
    const int r2 = r1 % 256;
    const int ks = r2 / 32;
    const int lane = r2 % 32;
    const int g = lane >> 2, tg = lane & 3;
    const int n = nt * 8 + g;
    const int k0 = ks * 8 + tg;
    const float* W = linW + (size_t)l * 4096;
    const float w0 = W[k0 * 64 + n];
    const float w4 = W[(k0 + 4) * 64 + n];
    const unsigned h0 = f2tf32(w0), h4 = f2tf32(w4);
    float4 o;
    o.x = __uint_as_float(h0);
    o.y = __uint_as_float(h4);
    o.z = __uint_as_float(f2tf32(w0 - __uint_as_float(h0)));
    o.w = __uint_as_float(f2tf32(w4 - __uint_as_float(h4)));
    *reinterpret_cast<float4*>(&g_wlin[(size_t)idx * 4]) = o;
}

// ---------------- pack proj (W transposed, K=128) ----------------
__global__ void packproj_kernel(const float* __restrict__ projW) {
    const int idx = blockIdx.x * 256 + threadIdx.x;  // 4096
    if (idx >= 8 * 16 * 32) return;
    const int nt = idx / 512;
    const int r = idx % 512;
    const int ks = r / 32;
    const int lane = r % 32;
    const int g = lane >> 2, tg = lane & 3;
    const int n = nt * 8 + g;
    const int k0 = ks * 8 + tg;
    const float w0 = projW[k0 * 64 + n];
    const float w4 = projW[(k0 + 4) * 64 + n];
    const unsigned h0 = f2tf32(w0), h4 = f2tf32(w4);
    float4 o;
    o.x = __uint_as_float(h0);
    o.y = __uint_as_float(h4);
    o.z = __uint_as_float(f2tf32(w0 - __uint_as_float(h0)));
    o.w = __uint_as_float(f2tf32(w4 - __uint_as_float(h4)));
    *reinterpret_cast<float4*>(&g_wproj[(size_t)idx * 4]) = o;
}

// ---------------- combined degree(row) + count(col) ----------------
__global__ void count_kernel(const int* __restrict__ rowI, const int* __restrict__ colI) {
    int s = gridDim.x * blockDim.x;
    for (int e = blockIdx.x * blockDim.x + threadIdx.x; e < EE; e += s) {
        atomicAdd(&g_cntR[rowI[e]], 1);
        atomicAdd(&g_cnt[colI[e]], 1);
    }
}
__global__ void finalize_deg_kernel() {
    int s = gridDim.x * blockDim.x;
    for (int n = blockIdx.x * blockDim.x + threadIdx.x; n < NN; n += s) {
        float dv = (float)g_cntR[n] + 1.f;
        g_deg[n] = dv;
        g_dinv[n] = rsqrtf(dv);
    }
}

// ---------------- CSR scan ----------------
__global__ void __launch_bounds__(256) scan1_kernel() {
    __shared__ int wsum[8];
    const int b = blockIdx.x;
    const int base = b * 1024;
    const int t = threadIdx.x;
    const int lane = t & 31, w = t >> 5;
    int v[4];
    const int idx0 = base + t * 4;
#pragma unroll
    for (int i = 0; i < 4; i++) {
        const int ii = idx0 + i;
        v[i] = (ii < NN) ? g_cnt[ii] : 0;
    }
    const int local = v[0] + v[1] + v[2] + v[3];
    int x = local;
#pragma unroll
    for (int off = 1; off < 32; off <<= 1) {
        int y = __shfl_up_sync(0xffffffffu, x, off);
        if (lane >= off) x += y;
    }
    if (lane == 31) wsum[w] = x;
    __syncthreads();
    if (t == 0) {
        int s = 0;
#pragma unroll
        for (int i = 0; i < 8; i++) { int tmp = wsum[i]; wsum[i] = s; s += tmp; }
        g_bsum[b] = s;
    }
    __syncthreads();
    int run = x - local + wsum[w];
#pragma unroll
    for (int i = 0; i < 4; i++) {
        const int ii = idx0 + i;
        if (ii < NN) g_coff[ii] = run;
        run += v[i];
    }
}
__global__ void scan2_kernel(int nb) {
    if (threadIdx.x == 0 && blockIdx.x == 0) {
        int s = 0;
        for (int i = 0; i < nb; i++) { int t = g_bsum[i]; g_bsum[i] = s; s += t; }
    }
}
__global__ void scan3_kernel() {
    int i = blockIdx.x * blockDim.x + threadIdx.x;
    int s = gridDim.x * blockDim.x;
    for (; i < NN; i += s) {
        const int vv = g_coff[i] + g_bsum[i >> 10];
        g_coff[i] = vv;
        g_cur[i] = vv;
    }
    if (blockIdx.x == 0 && threadIdx.x == 0) g_coff[NN] = EE;
}

// ---------------- fill: permute payloads into CSR order ----------------
__global__ void fill_kernel(const int* __restrict__ rowI, const int* __restrict__ colI,
                            const float* __restrict__ eattr) {
    int s = gridDim.x * blockDim.x;
    for (int e = blockIdx.x * blockDim.x + threadIdx.x; e < EE; e += s) {
        const int c = colI[e];
        const int r = rowI[e];
        const int pos = atomicAdd(&g_cur[c], 1);
        g_erow[pos] = r;
        g_nrm[pos] = g_dinv[r] * g_dinv[c];
        const float4* src = reinterpret_cast<const float4*>(eattr + (size_t)e * 16);
        float4* dst = reinterpret_cast<float4*>(g_eattrp + (size_t)pos * 16);
        dst[0] = __ldg(&src[0]);
        dst[1] = __ldg(&src[1]);
        dst[2] = __ldg(&src[2]);
        dst[3] = __ldg(&src[3]);
    }
}

// ---------------- edge-attr second-moment stats ----------------
__global__ void __launch_bounds__(256) stats_kernel(const float* __restrict__ eattr) {
    const int tid = threadIdx.x;
    const int parity = tid & 1;
    const int pair0 = (blockIdx.x * 256 + tid) >> 1;
    const int npairs = (gridDim.x * 256) >> 1;
    float sAcc[68];
    float mAcc[8];
#pragma unroll
    for (int i = 0; i < 68; i++) sAcc[i] = 0.f;
#pragma unroll
    for (int i = 0; i < 8; i++) mAcc[i] = 0.f;

    for (int e = pair0; e < EE; e += npairs) {
        const float4* ap = reinterpret_cast<const float4*>(eattr + (size_t)e * 16);
        float4 v0 = __ldg(&ap[0]), v1 = __ldg(&ap[1]), v2 = __ldg(&ap[2]), v3 = __ldg(&ap[3]);
        float a[16];
        a[0]=v0.x; a[1]=v0.y; a[2]=v0.z; a[3]=v0.w;
        a[4]=v1.x; a[5]=v1.y; a[6]=v1.z; a[7]=v1.w;
        a[8]=v2.x; a[9]=v2.y; a[10]=v2.z; a[11]=v2.w;
        a[12]=v3.x; a[13]=v3.y; a[14]=v3.z; a[15]=v3.w;
#pragma unroll
        for (int i = 0; i < 16; i++)
            if ((i >> 3) == parity) mAcc[i & 7] += a[i];
        int p = 0;
#pragma unroll
        for (int k = 0; k < 16; k++)
#pragma unroll
            for (int l = k; l < 16; l++) {
                if ((p & 1) == parity) sAcc[p >> 1] += a[k] * a[l];
                p++;
            }
    }
#pragma unroll
    for (int off = 16; off >= 2; off >>= 1) {
#pragma unroll
        for (int i = 0; i < 68; i++) sAcc[i] += __shfl_down_sync(0xffffffffu, sAcc[i], off);
#pragma unroll
        for (int i = 0; i < 8; i++) mAcc[i] += __shfl_down_sync(0xffffffffu, mAcc[i], off);
    }
    const int lane = tid & 31;
    if (lane < 2) {
#pragma unroll
        for (int i = 0; i < 68; i++) atomicAdd(&g_stats[i * 2 + lane], sAcc[i]);
#pragma unroll
        for (int i = 0; i < 8; i++) atomicAdd(&g_stats[136 + lane * 8 + i], mAcc[i]);
    }
}

// ---------------- fold bond Linear + BatchNorm into W', b' ----------------
__global__ void bondprep_kernel(const float* __restrict__ Wl, const float* __restrict__ bl,
                                const float* __restrict__ gl, const float* __restrict__ betal) {
    const int j = threadIdx.x;
    const float invE = 1.f / (float)EE;
    float w[16];
#pragma unroll
    for (int k = 0; k < 16; k++) w[k] = Wl[k * 64 + j];
    float dot_mw = 0.f;
#pragma unroll
    for (int k = 0; k < 16; k++) dot_mw += (g_stats[136 + k] * invE) * w[k];
    float quad = 0.f;
    int p = 0;
#pragma unroll
    for (int k = 0; k < 16; k++)
#pragma unroll
        for (int l = k; l < 16; l++) {
            const float s = g_stats[p++] * invE;
            quad += (k == l ? w[k] * w[l] : 2.f * w[k] * w[l]) * s;
        }
    const float b = bl[j];
    const float mean = dot_mw + b;
    const float e2 = quad + 2.f * b * dot_mw + b * b;
    const float var = e2 - mean * mean;
    const float scale = gl[j] * rsqrtf(var + 1e-6f);
#pragma unroll
    for (int k = 0; k < 16; k++) g_Wp[k * 64 + j] = w[k] * scale;
    g_bp[j] = (b - mean) * scale + betal[j];
}

// ---------------- proj GEMM with fused atom encoder (tf32 mma) ----------------
__global__ void __launch_bounds__(256) proj_mma_kernel(const float* __restrict__ ax,
                                                       const int* __restrict__ feat,
                                                       const float* __restrict__ emb,
                                                       const float* __restrict__ bias, int M) {
    __shared__ float As[64 * 132];
    const int tid = threadIdx.x;
    const int rowBase = blockIdx.x * 64;
#pragma unroll
    for (int idx = tid; idx < 64 * 32; idx += 256) {
        const int r = idx >> 5;
        const int c4 = idx & 31;
        const int gr = rowBase + r;
        float4 v = make_float4(0.f, 0.f, 0.f, 0.f);
        if (gr < M) {
            if (c4 < 16) {
                v = __ldg(reinterpret_cast<const float4*>(&ax[(size_t)gr * 64 + c4 * 4]));
            } else {
                const int d = (c4 - 16) * 4;
#pragma unroll
                for (int f = 0; f < 9; f++) {
                    const int fv = __ldg(&feat[gr * 9 + f]);
                    const float4 ev =
                        __ldg(reinterpret_cast<const float4*>(&emb[(f * 16 + fv) * 64 + d]));
                    v.x += ev.x; v.y += ev.y; v.z += ev.z; v.w += ev.w;
                }
            }
        }
        *reinterpret_cast<float4*>(&As[r * 132 + c4 * 4]) = v;
    }
    __syncthreads();
    mma_gemm_store<16, 132>(As, g_wproj, bias, g_h, M, rowBase, tid >> 5, tid & 31);
}

// ---------------- lin GEMM (tf32 mma), optional fused BN+relu on A ----------------
template <int MODE>  // 0 plain, 1 BN(scale/shift)+relu
__global__ void __launch_bounds__(256) lin_mma_kernel(const float* __restrict__ H,
                                                      const float* __restrict__ wpack,
                                                      const float* __restrict__ bias, int M) {
    __shared__ float As[64 * 68];
    const int tid = threadIdx.x;
    const int rowBase = blockIdx.x * 64;
#pragma unroll
    for (int idx = tid; idx < 64 * 16; idx += 256) {
        const int r = idx >> 4;
        const int c4 = idx & 15;
        const int gr = rowBase + r;
        float4 v = make_float4(0.f, 0.f, 0.f, 0.f);
        if (gr < M) {
            v = *reinterpret_cast<const float4*>(&H[(size_t)gr * 64 + c4 * 4]);
            if (MODE == 1) {
                const int d = c4 * 4;
                v.x = fmaxf(v.x * g_bnscale[d + 0] + g_bnshift[d + 0], 0.f);
                v.y = fmaxf(v.y * g_bnscale[d + 1] + g_bnshift[d + 1], 0.f);
                v.z = fmaxf(v.z * g_bnscale[d + 2] + g_bnshift[d + 2], 0.f);
                v.w = fmaxf(v.w * g_bnscale[d + 3] + g_bnshift[d + 3], 0.f);
            }
        }
        *reinterpret_cast<float4*>(&As[r * 68 + c4 * 4]) = v;
    }
    __syncthreads();
    mma_gemm_store<8, 68>(As, wpack, bias, g_x, M, rowBase, tid >> 5, tid & 31);
}

// ---------------- CSR gather (16 thr/node, float4, W' in regs; edge loop unroll-2) -------
__global__ void __launch_bounds__(256) gather_kernel() {
    const int tid = threadIdx.x;
    const int t = tid & 15;
    const int nloc = tid >> 4;
    const int n = blockIdx.x * 16 + nloc;
    float4 wreg[16];
#pragma unroll
    for (int k = 0; k < 16; k++)
        wreg[k] = *reinterpret_cast<const float4*>(&g_Wp[k * 64 + t * 4]);
    const float4 bb = *reinterpret_cast<const float4*>(&g_bp[t * 4]);
    if (n >= NN) return;
    const int jb = g_coff[n];
    const int je = g_coff[n + 1];
    float4 acc = make_float4(0.f, 0.f, 0.f, 0.f);
    int j = jb;
#pragma unroll 1
    for (; j + 2 <= je; j += 2) {
        const int r0 = __ldg(&g_erow[j]);
        const int r1 = __ldg(&g_erow[j + 1]);
        const float nrm0 = __ldg(&g_nrm[j]);
        const float nrm1 = __ldg(&g_nrm[j + 1]);
        const float4* ap0 = reinterpret_cast<const float4*>(g_eattrp + (size_t)j * 16);
        const float4* ap1 = reinterpret_cast<const float4*>(g_eattrp + (size_t)(j + 1) * 16);
        float4 m0 = bb, m1 = bb;
#pragma unroll
        for (int q = 0; q < 4; q++) {
            const float4 a0 = __ldg(&ap0[q]);
            const float4 a1 = __ldg(&ap1[q]);
            const float4 w0 = wreg[4 * q + 0];
            const float4 w1 = wreg[4 * q + 1];
            const float4 w2 = wreg[4 * q + 2];
            const float4 w3 = wreg[4 * q + 3];
            m0.x = fmaf(a0.x, w0.x, fmaf(a0.y, w1.x, fmaf(a0.z, w2.x, fmaf(a0.w, w3.x, m0.x))));
            m0.y = fmaf(a0.x, w0.y, fmaf(a0.y, w1.y, fmaf(a0.z, w2.y, fmaf(a0.w, w3.y, m0.y))));
            m0.z = fmaf(a0.x, w0.z, fmaf(a0.y, w1.z, fmaf(a0.z, w2.z, fmaf(a0.w, w3.z, m0.z))));
            m0.w = fmaf(a0.x, w0.w, fmaf(a0.y, w1.w, fmaf(a0.z, w2.w, fmaf(a0.w, w3.w, m0.w))));
            m1.x = fmaf(a1.x, w0.x, fmaf(a1.y, w1.x, fmaf(a1.z, w2.x, fmaf(a1.w, w3.x, m1.x))));
            m1.y = fmaf(a1.x, w0.y, fmaf(a1.y, w1.y, fmaf(a1.z, w2.y, fmaf(a1.w, w3.y, m1.y))));
            m1.z = fmaf(a1.x, w0.z, fmaf(a1.y, w1.z, fmaf(a1.z, w2.z, fmaf(a1.w, w3.z, m1.z))));
            m1.w = fmaf(a1.x, w0.w, fmaf(a1.y, w1.w, fmaf(a1.z, w2.w, fmaf(a1.w, w3.w, m1.w))));
        }
        const float4 x0 = __ldg(reinterpret_cast<const float4*>(&g_x[(size_t)r0 * 64 + t * 4]));
        const float4 x1 = __ldg(reinterpret_cast<const float4*>(&g_x[(size_t)r1 * 64 + t * 4]));
        acc.x = fmaf(nrm0, fmaxf(m0.x + x0.x, 0.f), acc.x);
        acc.y = fmaf(nrm0, fmaxf(m0.y + x0.y, 0.f), acc.y);
        acc.z = fmaf(nrm0, fmaxf(m0.z + x0.z, 0.f), acc.z);
        acc.w = fmaf(nrm0, fmaxf(m0.w + x0.w, 0.f), acc.w);
        acc.x = fmaf(nrm1, fmaxf(m1.x + x1.x, 0.f), acc.x);
        acc.y = fmaf(nrm1, fmaxf(m1.y + x1.y, 0.f), acc.y);
        acc.z = fmaf(nrm1, fmaxf(m1.z + x1.z, 0.f), acc.z);
        acc.w = fmaf(nrm1, fmaxf(m1.w + x1.w, 0.f), acc.w);
    }
    if (j < je) {
        const int r = __ldg(&g_erow[j]);
        const float nrm = __ldg(&g_nrm[j]);
        const float4* ap = reinterpret_cast<const float4*>(g_eattrp + (size_t)j * 16);
        float4 m = bb;
#pragma unroll
        for (int q = 0; q < 4; q++) {
            const float4 a = __ldg(&ap[q]);
            const float4 w0 = wreg[4 * q + 0];
            const float4 w1 = wreg[4 * q + 1];
            const float4 w2 = wreg[4 * q + 2];
            const float4 w3 = wreg[4 * q + 3];
            m.x = fmaf(a.x, w0.x, fmaf(a.y, w1.x, fmaf(a.z, w2.x, fmaf(a.w, w3.x, m.x))));
            m.y = fmaf(a.x, w0.y, fmaf(a.y, w1.y, fmaf(a.z, w2.y, fmaf(a.w, w3.y, m.y))));
            m.z = fmaf(a.x, w0.z, fmaf(a.y, w1.z, fmaf(a.z, w2.z, fmaf(a.w, w3.z, m.z))));
            m.w = fmaf(a.x, w0.w, fmaf(a.y, w1.w, fmaf(a.z, w2.w, fmaf(a.w, w3.w, m.w))));
        }
        const float4 xv = __ldg(reinterpret_cast<const float4*>(&g_x[(size_t)r * 64 + t * 4]));
        acc.x = fmaf(nrm, fmaxf(m.x + xv.x, 0.f), acc.x);
        acc.y = fmaf(nrm, fmaxf(m.y + xv.y, 0.f), acc.y);
        acc.z = fmaf(nrm, fmaxf(m.z + xv.z, 0.f), acc.z);
        acc.w = fmaf(nrm, fmaxf(m.w + xv.w, 0.f), acc.w);
    }
    *reinterpret_cast<float4*>(&g_aggr[(size_t)n * 64 + t * 4]) = acc;
}

// ---------------- fused GRU with tf32 HMMA (3xTF32) ----------------
__global__ void __launch_bounds__(256, 1) grumma_kernel(
    const float* __restrict__ bih, const float* __restrict__ bhh,
    const float* __restrict__ root, const float* __restrict__ wpackI,
    const float* __restrict__ wpackH, int M) {
    extern __shared__ float smem[];
    float* Aag = smem;
    float* Ax = Aag + 64 * 68;
    float* Sgi = Ax + 64 * 68;
    float* Sgh = Sgi + 64 * 196;
    float* ssum = Sgh + 64 * 196;
    float* ssq = ssum + 64;

    const int tid = threadIdx.x;
    const int w = tid >> 5;
    const int lane = tid & 31;
    const int rowBase = blockIdx.x * 64;

#pragma unroll
    for (int idx = tid; idx < 64 * 16; idx += 256) {
        const int r = idx >> 4;
        const int c4 = idx & 15;
        const int gr = rowBase + r;
        float4 va = make_float4(0.f, 0.f, 0.f, 0.f);
        float4 vx = make_float4(0.f, 0.f, 0.f, 0.f);
        if (gr < M) {
            va = *reinterpret_cast<const float4*>(&g_aggr[(size_t)gr * 64 + c4 * 4]);
            vx = *reinterpret_cast<const float4*>(&g_x[(size_t)gr * 64 + c4 * 4]);
        }
        *reinterpret_cast<float4*>(&Aag[r * 68 + c4 * 4]) = va;
        *reinterpret_cast<float4*>(&Ax[r * 68 + c4 * 4]) = vx;
    }
    if (tid < 64) { ssum[tid] = 0.f; ssq[tid] = 0.f; }
    __syncthreads();

    const int mrow = w & 3;
    const int ntbase = (w >> 2) * 12;
    const int g = lane >> 2, tg = lane & 3;

#pragma unroll
    for (int which = 0; which < 2; which++) {
        const float* A = (which == 0) ? Aag : Ax;
        const float* wp = (which == 0) ? wpackI : wpackH;
        float* S = (which == 0) ? Sgi : Sgh;

        float accs[12][4];
#pragma unroll
        for (int j = 0; j < 12; j++)
#pragma unroll
            for (int q = 0; q < 4; q++) accs[j][q] = 0.f;

#pragma unroll
        for (int ks = 0; ks < 8; ks++) {
            const int k0 = ks * 8;
            const float af[4] = {A[(mrow * 16 + g) * 68 + k0 + tg],
                                 A[(mrow * 16 + g + 8) * 68 + k0 + tg],
                                 A[(mrow * 16 + g) * 68 + k0 + tg + 4],
                                 A[(mrow * 16 + g + 8) * 68 + k0 + tg + 4]};
            unsigned ah[4], al[4];
#pragma unroll
            for (int q = 0; q < 4; q++) {
                ah[q] = f2tf32(af[q]);
                al[q] = f2tf32(af[q] - __uint_as_float(ah[q]));
            }
#pragma unroll
            for (int j = 0; j < 12; j++) {
                const int nt = ntbase + j;
                const float4 b =
                    __ldg(reinterpret_cast<const float4*>(&wp[(((size_t)nt * 8 + ks) * 32 + lane) * 4]));
                const unsigned bh0 = __float_as_uint(b.x);
                const unsigned bh4 = __float_as_uint(b.y);
                const unsigned bl0 = __float_as_uint(b.z);
                const unsigned bl4 = __float_as_uint(b.w);
                mma_tf32(accs[j], ah[0], ah[1], ah[2], ah[3], bh0, bh4);
                mma_tf32(accs[j], al[0], al[1], al[2], al[3], bh0, bh4);
                mma_tf32(accs[j], ah[0], ah[1], ah[2], ah[3], bl0, bl4);
            }
        }
#pragma unroll
        for (int j = 0; j < 12; j++) {
            const int n0 = (ntbase + j) * 8;
            const int r0 = mrow * 16 + g;
            *reinterpret_cast<float2*>(&S[r0 * 196 + n0 + tg * 2]) =
                make_float2(accs[j][0], accs[j][1]);
            *reinterpret_cast<float2*>(&S[(r0 + 8) * 196 + n0 + tg * 2]) =
                make_float2(accs[j][2], accs[j][3]);
        }
    }
    __syncthreads();

    const int tx = tid & 15;
    const int ty = tid >> 4;
    float ls[4] = {0.f, 0.f, 0.f, 0.f};
    float ls2[4] = {0.f, 0.f, 0.f, 0.f};
#pragma unroll
    for (int ri = 0; ri < 4; ri++) {
        const int r = ty * 4 + ri;
        const int row = rowBase + r;
        if (row < M) {
            const float dg = __ldg(&g_deg[row]);
#pragma unroll
            for (int di = 0; di < 4; di++) {
                const int d = di * 16 + tx;
                const float ir = Sgi[r * 196 + d] + __ldg(&bih[d]);
                const float iz = Sgi[r * 196 + 64 + d] + __ldg(&bih[64 + d]);
                const float inn = Sgi[r * 196 + 128 + d] + __ldg(&bih[128 + d]);
                const float hr = Sgh[r * 196 + d] + __ldg(&bhh[d]);
                const float hz = Sgh[r * 196 + 64 + d] + __ldg(&bhh[64 + d]);
                const float hn = Sgh[r * 196 + 128 + d] + __ldg(&bhh[128 + d]);
                const float xv = Ax[r * 68 + d];
                const float rr = 1.f / (1.f + expf(-(ir + hr)));
                const float z = 1.f / (1.f + expf(-(iz + hz)));
                const float nn2 = tanhf(inn + rr * hn);
                const float upd = (1.f - z) * nn2 + z * xv;
                const float hl = upd + fmaxf(xv + __ldg(&root[d]), 0.f) / dg;
                g_h[(size_t)row * 64 + d] = hl;
                ls[di] += hl;
                ls2[di] += hl * hl;
            }
        }
    }
#pragma unroll
    for (int di = 0; di < 4; di++) {
        atomicAdd(&ssum[di * 16 + tx], ls[di]);
        atomicAdd(&ssq[di * 16 + tx], ls2[di]);
    }
    __syncthreads();
    if (tid < 64) {
        atomicAdd(&g_bnstats[tid], ssum[tid]);
        atomicAdd(&g_bnstats[64 + tid], ssq[tid]);
    }
}

// ---------------- finalize BN stats -> scale/shift; reset stats for next layer ----------
__global__ void bnfin_kernel(const float* __restrict__ gamma, const float* __restrict__ beta) {
    const int d = threadIdx.x;  // 64
    const float invN = 1.f / (float)NN;
    const float mean = g_bnstats[d] * invN;
    const float var = g_bnstats[64 + d] * invN - mean * mean;
    const float sc = gamma[d] * rsqrtf(var + 1e-5f);
    g_bnscale[d] = sc;
    g_bnshift[d] = beta[d] - mean * sc;
    g_bnstats[d] = 0.f;
    g_bnstats[64 + d] = 0.f;
}

// ---------------- final output: BN apply (no relu) ----------------
__global__ void __launch_bounds__(256) bnout_kernel(float* __restrict__ out) {
    const int start = blockIdx.x * 256 + threadIdx.x;
    const int stride = gridDim.x * 256;
    for (int idx = start; idx < NN * 64; idx += stride) {
        const int d = idx & 63;
        out[idx] = g_h[idx] * g_bnscale[d] + g_bnshift[d];
    }
}

// ---------------- launch (3-stream fork/join) ----------------
extern "C" void kernel_launch(void* const* d_in, const int* in_sizes, int n_in,
                              void* d_out, int out_size) {
    const float* atom_x = (const float*)d_in[0];
    const int* atom_feature = (const int*)d_in[1];
    const int* edge_index = (const int*)d_in[2];
    const float* edge_attr = (const float*)d_in[3];
    const float* atom_emb = (const float*)d_in[4];
    const float* proj_W = (const float*)d_in[5];
    const float* proj_b = (const float*)d_in[6];
    const float* lin_W = (const float*)d_in[7];
    const float* lin_b = (const float*)d_in[8];
    const float* root_emb = (const float*)d_in[9];
    const float* bond_W = (const float*)d_in[10];
    const float* bond_b = (const float*)d_in[11];
    const float* bond_g = (const float*)d_in[12];
    const float* bond_beta = (const float*)d_in[13];
    const float* gru_Wih = (const float*)d_in[14];
    const float* gru_bih = (const float*)d_in[15];
    const float* gru_Whh = (const float*)d_in[16];
    const float* gru_bhh = (const float*)d_in[17];
    const float* bn_g = (const float*)d_in[18];
    const float* bn_b = (const float*)d_in[19];
    const int* rowI = edge_index;
    const int* colI = edge_index + EE;
    float* out = (float*)d_out;

    float *p_h, *p_stats, *p_bnstats, *p_wpack, *p_wlin;
    int *p_cnt, *p_cntR;
    cudaGetSymbolAddress((void**)&p_h, g_h);
    cudaGetSymbolAddress((void**)&p_stats, g_stats);
    cudaGetSymbolAddress((void**)&p_bnstats, g_bnstats);
    cudaGetSymbolAddress((void**)&p_cnt, g_cnt);
    cudaGetSymbolAddress((void**)&p_cntR, g_cntR);
    cudaGetSymbolAddress((void**)&p_wpack, g_wpack);
    cudaGetSymbolAddress((void**)&p_wlin, g_wlin);

    static cudaStream_t st1 = nullptr, st2 = nullptr;
    static cudaEvent_t evFork = nullptr, evJ1 = nullptr, evJ2 = nullptr;
    static int inited = 0;
    const int gruSmem = (2 * 64 * 68 + 2 * 64 * 196 + 128) * 4;
    if (!inited) {
        cudaFuncSetAttribute(grumma_kernel, cudaFuncAttributeMaxDynamicSharedMemorySize,
                             gruSmem);
        cudaStreamCreateWithFlags(&st1, cudaStreamNonBlocking);
        cudaStreamCreateWithFlags(&st2, cudaStreamNonBlocking);
        cudaEventCreateWithFlags(&evFork, cudaEventDisableTiming);
        cudaEventCreateWithFlags(&evJ1, cudaEventDisableTiming);
        cudaEventCreateWithFlags(&evJ2, cudaEventDisableTiming);
        inited = 1;
    }

    const int nScanBlocks = (NN + 1023) / 1024;

    // fork point (no prior work on default stream this launch)
    cudaEventRecord(evFork, 0);
    cudaStreamWaitEvent(st1, evFork, 0);
    cudaStreamWaitEvent(st2, evFork, 0);

    // stream 0: CSR chain
    zeroi_kernel<<<256, 256>>>(p_cnt, NN);
    zeroi_kernel<<<256, 256>>>(p_cntR, NN);
    count_kernel<<<1024, 256>>>(rowI, colI);
    finalize_deg_kernel<<<256, 256>>>();
    scan1_kernel<<<nScanBlocks, 256>>>();
    scan2_kernel<<<1, 32>>>(nScanBlocks);
    scan3_kernel<<<256, 256>>>();
    fill_kernel<<<1024, 256>>>(rowI, colI, edge_attr);

    // stream 1: stats (with its own zero) + initial bnstats zero (off critical path)
    zero_kernel<<<1, 256, 0, st1>>>(p_stats, 152);
    zero_kernel<<<1, 128, 0, st1>>>(p_bnstats, 128);
    stats_kernel<<<296, 256, 0, st1>>>(edge_attr);
    cudaEventRecord(evJ1, st1);

    // stream 2: packs -> proj -> lin0
    packw_kernel<<<144, 256, 0, st2>>>(gru_Wih, gru_Whh);
    packlin_kernel<<<24, 256, 0, st2>>>(lin_W);
    packproj_kernel<<<16, 256, 0, st2>>>(proj_W);
    proj_mma_kernel<<<1563, 256, 0, st2>>>(atom_x, atom_feature, atom_emb, proj_b, NN);
    lin_mma_kernel<0><<<1563, 256, 0, st2>>>(p_h, p_wlin, lin_b, NN);
    cudaEventRecord(evJ2, st2);

    // join on default stream
    cudaStreamWaitEvent(0, evJ1, 0);
    cudaStreamWaitEvent(0, evJ2, 0);

    for (int l = 0; l < 3; l++) {
        if (l > 0)
            lin_mma_kernel<1><<<1563, 256>>>(p_h, p_wlin + (size_t)l * 8192, lin_b + l * 64, NN);
        bondprep_kernel<<<1, 64>>>(bond_W + l * 16 * 64, bond_b + l * 64, bond_g + l * 64,
                                   bond_beta + l * 64);
        gather_kernel<<<(NN + 15) / 16, 256>>>();
        grumma_kernel<<<1563, 256, gruSmem>>>(gru_bih + l * 192, gru_bhh + l * 192,
                                              root_emb + l * 64,
                                              p_wpack + (size_t)(l * 2 + 0) * 24576,
                                              p_wpack + (size_t)(l * 2 + 1) * 24576, NN);
        bnfin_kernel<<<1, 64>>>(bn_g + l * 64, bn_b + l * 64);
    }
    bnout_kernel<<<512, 256>>>(out);
}